// round 4
// baseline (speedup 1.0000x reference)
#include <cuda_runtime.h>
#include <math.h>

#define Nn 50000
#define Ee 1600000
#define FIN 256
#define Hh 2
#define Dd 64
#define Kk 3
#define HD 128
#define NEG_SLOPE 0.2f
#define EPSf 1e-9f

// ---------------- scratch (device globals; no allocation allowed) -------------
__device__ float g_hsrc[Nn * HD];        // feat @ W_src           25.6MB
__device__ float g_hdst[Nn * HD];        // feat @ W_dst + b       25.6MB
__device__ float g_asrc[Nn * Hh];
__device__ float g_adst[Nn * Hh];
__device__ float g_dsum[Nn * Hh];        // sum of exp(e) per dst group
__device__ float g_ssum[Nn * Hh];        // ... per src group
__device__ float g_asort[Ee * Hh];       // attention coeffs in CSR(dst) order 12.8MB
__device__ int   g_colsrc[Ee];           // src node per CSR slot   6.4MB
__device__ int   g_posof[Ee];            // edge -> CSR slot        6.4MB
__device__ int   g_rowptr[Nn + 1];
__device__ int   g_fill[Nn];
__device__ float g_h0buf[Nn * HD];       // ping-pong raw h        25.6MB
__device__ float g_h1buf[Nn * HD];       //                        25.6MB
__device__ float g_hstack[(size_t)Nn * Hh * Kk * Dd]; // feat_trans'd hops 76.8MB
__device__ float g_al[Nn * Hh];          // hop-attn left term

// ---------------- helpers ----------------------------------------------------
__device__ __forceinline__ float lrelu(float x) { return x > 0.f ? x : NEG_SLOPE * x; }

// ---------------- init --------------------------------------------------------
__global__ void k_init() {
    int i = blockIdx.x * blockDim.x + threadIdx.x;
    if (i < Nn * Hh) { g_dsum[i] = 0.f; g_ssum[i] = 0.f; }
    if (i < Nn) g_fill[i] = 0;
    if (i <= Nn) g_rowptr[i] = 0;
}

// ---------------- fused dual GEMM: h_src / h_dst ------------------------------
// C[N,128] = A[N,256] @ W[256,128] (+bias for z==1). 64x64 tile, 256 thr, 4x4 micro.
__global__ void k_gemm(const float* __restrict__ A, const float* __restrict__ Ws,
                       const float* __restrict__ Wd, const float* __restrict__ bd) {
    const int which = blockIdx.z;
    const float* W = which ? Wd : Ws;
    float* C = which ? g_hdst : g_hsrc;

    __shared__ float sA[16][68];   // [k][m], padded
    __shared__ float sB[16][64];   // [k][n]

    int t = threadIdx.x;
    int ty = t >> 4, tx = t & 15;
    int rowBase = blockIdx.y * 64, colBase = blockIdx.x * 64;
    float acc[4][4] = {};

    int arow = t >> 2, acol = (t & 3) * 4;   // A tile: 64 rows x 16 k
    int brow = t >> 4, bcol = (t & 15) * 4;  // B tile: 16 k x 64 cols

    for (int k0 = 0; k0 < FIN; k0 += 16) {
        float4 av = make_float4(0.f, 0.f, 0.f, 0.f);
        int gr = rowBase + arow;
        if (gr < Nn) av = *(const float4*)(A + (size_t)gr * FIN + k0 + acol);
        sA[acol + 0][arow] = av.x; sA[acol + 1][arow] = av.y;
        sA[acol + 2][arow] = av.z; sA[acol + 3][arow] = av.w;
        *(float4*)&sB[brow][bcol] = *(const float4*)(W + (size_t)(k0 + brow) * HD + colBase + bcol);
        __syncthreads();
#pragma unroll
        for (int kk = 0; kk < 16; kk++) {
            float4 ra4 = *(float4*)&sA[kk][ty * 4];
            float4 rb4 = *(float4*)&sB[kk][tx * 4];
            float ra[4] = {ra4.x, ra4.y, ra4.z, ra4.w};
            float rb[4] = {rb4.x, rb4.y, rb4.z, rb4.w};
#pragma unroll
            for (int i = 0; i < 4; i++)
#pragma unroll
                for (int j = 0; j < 4; j++) acc[i][j] += ra[i] * rb[j];
        }
        __syncthreads();
    }
#pragma unroll
    for (int i = 0; i < 4; i++) {
        int gr = rowBase + ty * 4 + i;
        if (gr >= Nn) continue;
#pragma unroll
        for (int j = 0; j < 4; j++) {
            int gc = colBase + tx * 4 + j;
            float v = acc[i][j];
            if (which) v += bd[gc];
            C[(size_t)gr * HD + gc] = v;
        }
    }
}

// ---------------- attention projections (a_src, a_dst) ------------------------
// one warp per node: 4 dot-products of length 256
__global__ void k_attnproj(const float* __restrict__ feat,
                           const float* __restrict__ Was, const float* __restrict__ Wad) {
    __shared__ float sWs[FIN * Hh], sWd[FIN * Hh];
    int t = threadIdx.x;
    for (int i = t; i < FIN * Hh; i += blockDim.x) { sWs[i] = Was[i]; sWd[i] = Wad[i]; }
    __syncthreads();
    int w = blockIdx.x * (blockDim.x >> 5) + (t >> 5);
    if (w >= Nn) return;
    int lane = t & 31;
    const float4* fp = (const float4*)(feat + (size_t)w * FIN + lane * 8);
    float4 f0 = fp[0], f1 = fp[1];
    float fv[8] = {f0.x, f0.y, f0.z, f0.w, f1.x, f1.y, f1.z, f1.w};
    float as0 = 0, as1 = 0, ad0 = 0, ad1 = 0;
#pragma unroll
    for (int j = 0; j < 8; j++) {
        int k = lane * 8 + j;
        as0 += fv[j] * sWs[k * 2];  as1 += fv[j] * sWs[k * 2 + 1];
        ad0 += fv[j] * sWd[k * 2];  ad1 += fv[j] * sWd[k * 2 + 1];
    }
#pragma unroll
    for (int o = 16; o; o >>= 1) {
        as0 += __shfl_xor_sync(0xffffffffu, as0, o);
        as1 += __shfl_xor_sync(0xffffffffu, as1, o);
        ad0 += __shfl_xor_sync(0xffffffffu, ad0, o);
        ad1 += __shfl_xor_sync(0xffffffffu, ad1, o);
    }
    if (lane == 0) {
        g_asrc[w * 2] = as0; g_asrc[w * 2 + 1] = as1;
        g_adst[w * 2] = ad0; g_adst[w * 2 + 1] = ad1;
    }
}

// ---------------- CSR build ----------------------------------------------------
__global__ void k_hist(const int* __restrict__ dst) {
    int e = blockIdx.x * blockDim.x + threadIdx.x;
    if (e < Ee) atomicAdd(&g_rowptr[dst[e] + 1], 1);
}

// single-block inclusive scan over rowptr[0..N]
__global__ void k_scan() {
    __shared__ int sh[1024];
    __shared__ int carry;
    int tid = threadIdx.x;
    if (tid == 0) carry = 0;
    __syncthreads();
    const int n = Nn + 1;
    for (int base = 0; base < n; base += 1024) {
        int i = base + tid;
        int v = (i < n) ? g_rowptr[i] : 0;
        sh[tid] = v;
        __syncthreads();
        for (int off = 1; off < 1024; off <<= 1) {
            int tv = (tid >= off) ? sh[tid - off] : 0;
            __syncthreads();
            sh[tid] += tv;
            __syncthreads();
        }
        int out = sh[tid] + carry;
        if (i < n) g_rowptr[i] = out;
        __syncthreads();
        if (tid == 1023) carry = out;
        __syncthreads();
    }
}

__global__ void k_scatter(const int* __restrict__ src, const int* __restrict__ dst) {
    int e = blockIdx.x * blockDim.x + threadIdx.x;
    if (e >= Ee) return;
    int d = dst[e];
    int pos = g_rowptr[d] + atomicAdd(&g_fill[d], 1);
    g_colsrc[pos] = src[e];
    g_posof[e] = pos;
}

// ---------------- edge softmax (2 passes; exp without max-shift is safe: -------
// logits = leaky_relu(a_src+a_dst), |logit| <~ 8 for these input scales) -------
__global__ void k_edge_sum(const int* __restrict__ src, const int* __restrict__ dst) {
    int e = blockIdx.x * blockDim.x + threadIdx.x;
    if (e >= Ee) return;
    int s = src[e], d = dst[e];
    float2 as = ((const float2*)g_asrc)[s];
    float2 ad = ((const float2*)g_adst)[d];
    float x0 = __expf(lrelu(as.x + ad.x));
    float x1 = __expf(lrelu(as.y + ad.y));
    atomicAdd(&g_dsum[2 * d], x0);
    atomicAdd(&g_dsum[2 * d + 1], x1);
    atomicAdd(&g_ssum[2 * s], x0);
    atomicAdd(&g_ssum[2 * s + 1], x1);
}

__global__ void k_edge_coef(const int* __restrict__ src, const int* __restrict__ dst) {
    int e = blockIdx.x * blockDim.x + threadIdx.x;
    if (e >= Ee) return;
    int s = src[e], d = dst[e];
    float2 as = ((const float2*)g_asrc)[s];
    float2 ad = ((const float2*)g_adst)[d];
    float x0 = __expf(lrelu(as.x + ad.x));
    float x1 = __expf(lrelu(as.y + ad.y));
    float pd0 = x0 / g_dsum[2 * d], pd1 = x1 / g_dsum[2 * d + 1];
    float ps0 = x0 / g_ssum[2 * s], ps1 = x1 / g_ssum[2 * s + 1];
    float a0 = sqrtf(fmaxf(pd0, EPSf) * fmaxf(ps0, EPSf));
    float a1 = sqrtf(fmaxf(pd1, EPSf) * fmaxf(ps1, EPSf));
    ((float2*)g_asort)[g_posof[e]] = make_float2(a0, a1);
}

// ---------------- h0 feat_trans + hop-attn left term --------------------------
// one warp per (node, head)
__global__ void k_h0al(const float* __restrict__ scale, const float* __restrict__ offset,
                       const float* __restrict__ pemb,  const float* __restrict__ hal) {
    int w = blockIdx.x * (blockDim.x >> 5) + (threadIdx.x >> 5);
    if (w >= Nn * Hh) return;
    int n = w >> 1, head = w & 1;
    int lane = threadIdx.x & 31;
    float2 x = *(const float2*)(g_hsrc + (size_t)n * HD + head * Dd + lane * 2);
    float s = x.x + x.y, q = x.x * x.x + x.y * x.y;
#pragma unroll
    for (int o = 16; o; o >>= 1) {
        s += __shfl_xor_sync(0xffffffffu, s, o);
        q += __shfl_xor_sync(0xffffffffu, q, o);
    }
    float mean = s * (1.f / 64.f);
    float var  = q * (1.f / 64.f) - mean * mean + EPSf;
    float rs = rsqrtf(var);
    int bi = head * Dd + lane * 2;   // k = 0 slice
    float2 sc = *(const float2*)(scale + bi);
    float2 of = *(const float2*)(offset + bi);
    float2 pe = *(const float2*)(pemb + bi);
    float2 hl = *(const float2*)(hal + bi);
    float n0 = (x.x - mean) * sc.x * rs + of.x + pe.x;
    float n1 = (x.y - mean) * sc.y * rs + of.y + pe.y;
    float p = n0 * hl.x + n1 * hl.y;
#pragma unroll
    for (int o = 16; o; o >>= 1) p += __shfl_xor_sync(0xffffffffu, p, o);
    if (lane == 0) g_al[w] = p;
}

// ---------------- diffusion hop: pull-gather + fused feat_trans ----------------
// one warp per node; lane covers 4 of the 128 (H*D) floats.
// Edges chunked by 16: lane l preloads src/coef of edge base+(l&15), where the
// coef is the one for THIS lane's head (coef = asort[2*e + head], coalesced
// 128B across the warp). Broadcasting edge j uses source lane head*16+j, so
// each lane receives its own head's coefficient with a single shfl.
// x4 unroll keeps 4 independent LDG.128 in flight against L2 latency.
__global__ void k_hop(int hop, const float* __restrict__ scale,
                      const float* __restrict__ offset, const float* __restrict__ pemb) {
    int n = blockIdx.x * (blockDim.x >> 5) + (threadIdx.x >> 5);
    if (n >= Nn) return;
    int lane = threadIdx.x & 31;
    int head = lane >> 4;
    const float* __restrict__ hin = (hop == 0) ? g_hsrc : (hop == 1 ? g_h0buf : g_h1buf);
    float* hout = (hop & 1) ? g_h1buf : g_h0buf;

    int start = g_rowptr[n], end = g_rowptr[n + 1];
    int srcl = head << 4;  // shfl source base for this lane's head
    float4 acc = make_float4(0.f, 0.f, 0.f, 0.f);
    for (int base = start; base < end; base += 16) {
        int cnt = end - base; if (cnt > 16) cnt = 16;
        int el = lane & 15;
        int s = 0; float coef = 0.f;
        if (el < cnt) {
            int e = base + el;
            s    = g_colsrc[e];
            coef = g_asort[2 * e + head];
        }
        int j = 0;
        for (; j + 4 <= cnt; j += 4) {
            int   s0 = __shfl_sync(0xffffffffu, s, j);
            int   s1 = __shfl_sync(0xffffffffu, s, j + 1);
            int   s2 = __shfl_sync(0xffffffffu, s, j + 2);
            int   s3 = __shfl_sync(0xffffffffu, s, j + 3);
            float a0 = __shfl_sync(0xffffffffu, coef, srcl + j);
            float a1 = __shfl_sync(0xffffffffu, coef, srcl + j + 1);
            float a2 = __shfl_sync(0xffffffffu, coef, srcl + j + 2);
            float a3 = __shfl_sync(0xffffffffu, coef, srcl + j + 3);
            float4 v0 = *(const float4*)(hin + (size_t)s0 * HD + lane * 4);
            float4 v1 = *(const float4*)(hin + (size_t)s1 * HD + lane * 4);
            float4 v2 = *(const float4*)(hin + (size_t)s2 * HD + lane * 4);
            float4 v3 = *(const float4*)(hin + (size_t)s3 * HD + lane * 4);
            acc.x += a0 * v0.x + a1 * v1.x + a2 * v2.x + a3 * v3.x;
            acc.y += a0 * v0.y + a1 * v1.y + a2 * v2.y + a3 * v3.y;
            acc.z += a0 * v0.z + a1 * v1.z + a2 * v2.z + a3 * v3.z;
            acc.w += a0 * v0.w + a1 * v1.w + a2 * v2.w + a3 * v3.w;
        }
        for (; j < cnt; j++) {
            int   ss = __shfl_sync(0xffffffffu, s, j);
            float aa = __shfl_sync(0xffffffffu, coef, srcl + j);
            float4 v = *(const float4*)(hin + (size_t)ss * HD + lane * 4);
            acc.x += aa * v.x; acc.y += aa * v.y; acc.z += aa * v.z; acc.w += aa * v.w;
        }
    }
    *(float4*)(hout + (size_t)n * HD + lane * 4) = acc;   // raw h for next hop

    // fused feat_trans(k = hop+1): LayerNorm over D within half-warp (16 lanes)
    float s1 = acc.x + acc.y + acc.z + acc.w;
    float q1 = acc.x * acc.x + acc.y * acc.y + acc.z * acc.z + acc.w * acc.w;
#pragma unroll
    for (int o = 1; o < 16; o <<= 1) {
        s1 += __shfl_xor_sync(0xffffffffu, s1, o);
        q1 += __shfl_xor_sync(0xffffffffu, q1, o);
    }
    float mean = s1 * (1.f / 64.f);
    float var  = q1 * (1.f / 64.f) - mean * mean + EPSf;
    float rs = rsqrtf(var);
    int k = hop + 1;
    int d0 = (lane & 15) * 4;
    int pi = (k * Hh + head) * Dd + d0;
    float4 sc = *(const float4*)(scale + pi);
    float4 of = *(const float4*)(offset + pi);
    float4 pe = *(const float4*)(pemb + pi);
    float4 ov;
    ov.x = (acc.x - mean) * sc.x * rs + of.x + pe.x;
    ov.y = (acc.y - mean) * sc.y * rs + of.y + pe.y;
    ov.z = (acc.z - mean) * sc.z * rs + of.z + pe.z;
    ov.w = (acc.w - mean) * sc.w * rs + of.w + pe.w;
    *(float4*)(g_hstack + ((((size_t)n * Hh + head) * Kk) + hop) * Dd + d0) = ov;
}

// ---------------- hop attention + residual ------------------------------------
__global__ void k_final(const float* __restrict__ war, float* __restrict__ out) {
    int n = blockIdx.x * (blockDim.x >> 5) + (threadIdx.x >> 5);
    if (n >= Nn) return;
    int lane = threadIdx.x & 31;
    int head = lane >> 4, d0 = (lane & 15) * 4;
    float4 wr = *(const float4*)(war + head * Dd + d0);
    float al = g_al[n * 2 + head];
    float4 v[3]; float ha[3];
#pragma unroll
    for (int k = 0; k < 3; k++) {
        v[k] = *(const float4*)(g_hstack + ((((size_t)n * Hh + head) * Kk) + k) * Dd + d0);
        float p = v[k].x * wr.x + v[k].y * wr.y + v[k].z * wr.z + v[k].w * wr.w;
#pragma unroll
        for (int o = 1; o < 16; o <<= 1) p += __shfl_xor_sync(0xffffffffu, p, o);
        ha[k] = lrelu(p + al);
    }
    float m = fmaxf(ha[0], fmaxf(ha[1], ha[2]));
    float e0 = __expf(ha[0] - m), e1 = __expf(ha[1] - m), e2 = __expf(ha[2] - m);
    float inv = 1.f / (e0 + e1 + e2);
    float s0 = e0 * inv, s1 = e1 * inv, s2 = e2 * inv;
    float4 hd = *(const float4*)(g_hdst + (size_t)n * HD + lane * 4);
    float4 o4;
    o4.x = hd.x + s0 * v[0].x + s1 * v[1].x + s2 * v[2].x;
    o4.y = hd.y + s0 * v[0].y + s1 * v[1].y + s2 * v[2].y;
    o4.z = hd.z + s0 * v[0].z + s1 * v[1].z + s2 * v[2].z;
    o4.w = hd.w + s0 * v[0].w + s1 * v[1].w + s2 * v[2].w;
    *(float4*)(out + (size_t)n * HD + lane * 4) = o4;
}

// ---------------- launch -------------------------------------------------------
extern "C" void kernel_launch(void* const* d_in, const int* in_sizes, int n_in,
                              void* d_out, int out_size) {
    const float* feat  = (const float*)d_in[0];
    const int*   src   = (const int*)d_in[1];
    const int*   dst   = (const int*)d_in[2];
    const float* Wsrc  = (const float*)d_in[3];
    const float* Wdst  = (const float*)d_in[4];
    const float* bdst  = (const float*)d_in[5];
    const float* Was   = (const float*)d_in[6];
    const float* Wad   = (const float*)d_in[7];
    const float* scale = (const float*)d_in[8];
    const float* offs  = (const float*)d_in[9];
    const float* pemb  = (const float*)d_in[10];
    const float* hal   = (const float*)d_in[11];
    const float* war   = (const float*)d_in[12];
    float* out = (float*)d_out;
    (void)in_sizes; (void)n_in; (void)out_size;

    k_init<<<(Nn * Hh + 255) / 256, 256>>>();

    dim3 gg(HD / 64, (Nn + 63) / 64, 2);
    k_gemm<<<gg, 256>>>(feat, Wsrc, Wdst, bdst);
    k_attnproj<<<(Nn + 7) / 8, 256>>>(feat, Was, Wad);

    int eb = (Ee + 255) / 256;
    k_hist<<<eb, 256>>>(dst);
    k_scan<<<1, 1024>>>();
    k_scatter<<<eb, 256>>>(src, dst);

    k_edge_sum<<<eb, 256>>>(src, dst);
    k_edge_coef<<<eb, 256>>>(src, dst);

    k_h0al<<<(Nn * Hh + 7) / 8, 256>>>(scale, offs, pemb, hal);

    for (int hop = 0; hop < Kk; hop++)
        k_hop<<<(Nn + 7) / 8, 256>>>(hop, scale, offs, pemb);

    k_final<<<(Nn + 7) / 8, 256>>>(war, out);
}

// round 6
// speedup vs baseline: 1.1271x; 1.1271x over previous
#include <cuda_runtime.h>
#include <math.h>

#define Nn 50000
#define Ee 1600000
#define FIN 256
#define Hh 2
#define Dd 64
#define Kk 3
#define HD 128
#define NEG_SLOPE 0.2f
#define EPSf 1e-9f

// ---------------- scratch (device globals; no allocation allowed) -------------
__device__ float g_hsrc[Nn * HD];
__device__ float g_hdst[Nn * HD];
__device__ float g_asrc[Nn * Hh];
__device__ float g_adst[Nn * Hh];
__device__ float g_dsum[Nn * Hh];
__device__ float g_ssum[Nn * Hh];
__device__ float g_asort[Ee * Hh];
__device__ int   g_colsrc[Ee];
__device__ int   g_posof[Ee];
__device__ int   g_rowptr[Nn + 1];
__device__ int   g_fill[Nn];
__device__ float g_h0buf[Nn * HD];
__device__ float g_h1buf[Nn * HD];
__device__ float g_hstack[(size_t)Nn * Hh * Kk * Dd];
__device__ float g_al[Nn * Hh];

// ---------------- helpers ----------------------------------------------------
__device__ __forceinline__ float lrelu(float x) { return x > 0.f ? x : NEG_SLOPE * x; }

__device__ __forceinline__ unsigned long long packdup(float v) {
    unsigned long long r;
    asm("mov.b64 %0, {%1, %1};" : "=l"(r) : "f"(v));
    return r;
}
__device__ __forceinline__ void fma2(unsigned long long& acc, unsigned long long a,
                                     unsigned long long b) {
    asm("fma.rn.f32x2 %0, %1, %2, %0;" : "+l"(acc) : "l"(a), "l"(b));
}
__device__ __forceinline__ float2 unpk(unsigned long long v) {
    float lo, hi;
    asm("mov.b64 {%0, %1}, %2;" : "=f"(lo), "=f"(hi) : "l"(v));
    return make_float2(lo, hi);
}

// ---------------- init --------------------------------------------------------
__global__ void k_init() {
    int i = blockIdx.x * blockDim.x + threadIdx.x;
    if (i < Nn * Hh) { g_dsum[i] = 0.f; g_ssum[i] = 0.f; }
    if (i < Nn) g_fill[i] = 0;
    if (i <= Nn) g_rowptr[i] = 0;
}

// ---------------- fused dual GEMM: h_src / h_dst ------------------------------
// C[N,128] = A[N,256] @ W[256,128] (+bias for z==1).
// 128x128 tile, 256 threads, 8x8 micro, packed f32x2 FMA (2x FFMA rate on B300).
// Accumulators pair adjacent ROWS: aPair (a_i, a_i+1) comes directly from
// LDS.128 of [k][row]-major A tile; only b needs 8 dup-packs per kk.
__global__ void __launch_bounds__(256) k_gemm(const float* __restrict__ A,
                       const float* __restrict__ Ws, const float* __restrict__ Wd,
                       const float* __restrict__ bd) {
    const int which = blockIdx.z;
    const float* W = which ? Wd : Ws;
    float* C = which ? g_hdst : g_hsrc;

    __shared__ __align__(16) float sA[16][128];   // [k][row]
    __shared__ __align__(16) float sB[16][128];   // [k][col]

    int t = threadIdx.x;
    int ty = t >> 4, tx = t & 15;                 // ty->row group, tx->col group
    int rowBase = blockIdx.y * 128;

    unsigned long long acc[4][8];                 // [rowpair][col], f32x2 over rows
#pragma unroll
    for (int i = 0; i < 4; i++)
#pragma unroll
        for (int j = 0; j < 8; j++) acc[i][j] = 0ull;

    int arow = t >> 1, acol = (t & 1) * 8;        // A: 128 rows x 16 k per chunk
    int brow = t >> 4, bcol = (t & 15) * 8;       // B: 16 k x 128 cols per chunk

    for (int k0 = 0; k0 < FIN; k0 += 16) {
        int gr = rowBase + arow;
        float4 av0 = make_float4(0.f,0.f,0.f,0.f), av1 = av0;
        if (gr < Nn) {
            const float4* ap = (const float4*)(A + (size_t)gr * FIN + k0 + acol);
            av0 = ap[0]; av1 = ap[1];
        }
        sA[acol + 0][arow] = av0.x; sA[acol + 1][arow] = av0.y;
        sA[acol + 2][arow] = av0.z; sA[acol + 3][arow] = av0.w;
        sA[acol + 4][arow] = av1.x; sA[acol + 5][arow] = av1.y;
        sA[acol + 6][arow] = av1.z; sA[acol + 7][arow] = av1.w;
        {
            const float4* bp = (const float4*)(W + (size_t)(k0 + brow) * HD + bcol);
            *(float4*)&sB[brow][bcol + 0] = bp[0];
            *(float4*)&sB[brow][bcol + 4] = bp[1];
        }
        __syncthreads();
#pragma unroll
        for (int kk = 0; kk < 16; kk++) {
            // a pairs: rows ty*8 .. ty*8+7 as 4 f32x2 (adjacent rows packed)
            const ulonglong2* ap2 = (const ulonglong2*)&sA[kk][ty * 8];
            ulonglong2 apA = ap2[0], apB = ap2[1];
            unsigned long long aP[4] = {apA.x, apA.y, apB.x, apB.y};
            float4 b0 = *(const float4*)&sB[kk][tx * 8];
            float4 b1 = *(const float4*)&sB[kk][tx * 8 + 4];
            unsigned long long bD[8];
            bD[0] = packdup(b0.x); bD[1] = packdup(b0.y);
            bD[2] = packdup(b0.z); bD[3] = packdup(b0.w);
            bD[4] = packdup(b1.x); bD[5] = packdup(b1.y);
            bD[6] = packdup(b1.z); bD[7] = packdup(b1.w);
#pragma unroll
            for (int i = 0; i < 4; i++)
#pragma unroll
                for (int j = 0; j < 8; j++) fma2(acc[i][j], aP[i], bD[j]);
        }
        __syncthreads();
    }

    // epilogue: unpack row pairs, vectorized stores
    int colB = tx * 8;
    float bias[8];
#pragma unroll
    for (int j = 0; j < 8; j++) bias[j] = which ? bd[colB + j] : 0.f;
#pragma unroll
    for (int ip = 0; ip < 4; ip++) {
        int r0 = rowBase + ty * 8 + 2 * ip;
        float lo[8], hi[8];
#pragma unroll
        for (int j = 0; j < 8; j++) {
            float2 p = unpk(acc[ip][j]);
            lo[j] = p.x + bias[j]; hi[j] = p.y + bias[j];
        }
        if (r0 < Nn) {
            float4* cp = (float4*)(C + (size_t)r0 * HD + colB);
            cp[0] = make_float4(lo[0], lo[1], lo[2], lo[3]);
            cp[1] = make_float4(lo[4], lo[5], lo[6], lo[7]);
        }
        if (r0 + 1 < Nn) {
            float4* cp = (float4*)(C + (size_t)(r0 + 1) * HD + colB);
            cp[0] = make_float4(hi[0], hi[1], hi[2], hi[3]);
            cp[1] = make_float4(hi[4], hi[5], hi[6], hi[7]);
        }
    }
}

// ---------------- attention projections (a_src, a_dst) ------------------------
__global__ void k_attnproj(const float* __restrict__ feat,
                           const float* __restrict__ Was, const float* __restrict__ Wad) {
    __shared__ float sWs[FIN * Hh], sWd[FIN * Hh];
    int t = threadIdx.x;
    for (int i = t; i < FIN * Hh; i += blockDim.x) { sWs[i] = Was[i]; sWd[i] = Wad[i]; }
    __syncthreads();
    int w = blockIdx.x * (blockDim.x >> 5) + (t >> 5);
    if (w >= Nn) return;
    int lane = t & 31;
    const float4* fp = (const float4*)(feat + (size_t)w * FIN + lane * 8);
    float4 f0 = fp[0], f1 = fp[1];
    float fv[8] = {f0.x, f0.y, f0.z, f0.w, f1.x, f1.y, f1.z, f1.w};
    float as0 = 0, as1 = 0, ad0 = 0, ad1 = 0;
#pragma unroll
    for (int j = 0; j < 8; j++) {
        int k = lane * 8 + j;
        as0 += fv[j] * sWs[k * 2];  as1 += fv[j] * sWs[k * 2 + 1];
        ad0 += fv[j] * sWd[k * 2];  ad1 += fv[j] * sWd[k * 2 + 1];
    }
#pragma unroll
    for (int o = 16; o; o >>= 1) {
        as0 += __shfl_xor_sync(0xffffffffu, as0, o);
        as1 += __shfl_xor_sync(0xffffffffu, as1, o);
        ad0 += __shfl_xor_sync(0xffffffffu, ad0, o);
        ad1 += __shfl_xor_sync(0xffffffffu, ad1, o);
    }
    if (lane == 0) {
        g_asrc[w * 2] = as0; g_asrc[w * 2 + 1] = as1;
        g_adst[w * 2] = ad0; g_adst[w * 2 + 1] = ad1;
    }
}

// ---------------- CSR build ----------------------------------------------------
__global__ void k_hist(const int* __restrict__ dst) {
    int e = blockIdx.x * blockDim.x + threadIdx.x;
    if (e < Ee) atomicAdd(&g_rowptr[dst[e] + 1], 1);
}

// single-block scan, warp-shuffle based (4 syncs per 1024-chunk)
__global__ void k_scan() {
    __shared__ int warpsums[32];
    __shared__ int carry_sh;
    int tid = threadIdx.x, lane = tid & 31, wid = tid >> 5;
    if (tid == 0) carry_sh = 0;
    __syncthreads();
    const int n = Nn + 1;
    for (int base = 0; base < n; base += 1024) {
        int i = base + tid;
        int v = (i < n) ? g_rowptr[i] : 0;
#pragma unroll
        for (int o = 1; o < 32; o <<= 1) {
            int tv = __shfl_up_sync(0xffffffffu, v, o);
            if (lane >= o) v += tv;
        }
        if (lane == 31) warpsums[wid] = v;
        __syncthreads();
        if (wid == 0) {
            int wv = warpsums[lane];
#pragma unroll
            for (int o = 1; o < 32; o <<= 1) {
                int tv = __shfl_up_sync(0xffffffffu, wv, o);
                if (lane >= o) wv += tv;
            }
            warpsums[lane] = wv;
        }
        __syncthreads();
        int out = v + (wid > 0 ? warpsums[wid - 1] : 0) + carry_sh;
        if (i < n) g_rowptr[i] = out;
        __syncthreads();
        if (tid == 1023) carry_sh = out;
        __syncthreads();
    }
}

// ---------------- fused scatter + softmax denominator pass ---------------------
__global__ void k_scatter_sum(const int* __restrict__ src, const int* __restrict__ dst) {
    int e = blockIdx.x * blockDim.x + threadIdx.x;
    if (e >= Ee) return;
    int s = src[e], d = dst[e];
    int pos = g_rowptr[d] + atomicAdd(&g_fill[d], 1);
    g_colsrc[pos] = s;
    g_posof[e] = pos;
    float2 as = ((const float2*)g_asrc)[s];
    float2 ad = ((const float2*)g_adst)[d];
    float x0 = __expf(lrelu(as.x + ad.x));
    float x1 = __expf(lrelu(as.y + ad.y));
    atomicAdd(&g_dsum[2 * d], x0);
    atomicAdd(&g_dsum[2 * d + 1], x1);
    atomicAdd(&g_ssum[2 * s], x0);
    atomicAdd(&g_ssum[2 * s + 1], x1);
}

__global__ void k_edge_coef(const int* __restrict__ src, const int* __restrict__ dst) {
    int e = blockIdx.x * blockDim.x + threadIdx.x;
    if (e >= Ee) return;
    int s = src[e], d = dst[e];
    float2 as = ((const float2*)g_asrc)[s];
    float2 ad = ((const float2*)g_adst)[d];
    float x0 = __expf(lrelu(as.x + ad.x));
    float x1 = __expf(lrelu(as.y + ad.y));
    float pd0 = x0 / g_dsum[2 * d], pd1 = x1 / g_dsum[2 * d + 1];
    float ps0 = x0 / g_ssum[2 * s], ps1 = x1 / g_ssum[2 * s + 1];
    float a0 = sqrtf(fmaxf(pd0, EPSf) * fmaxf(ps0, EPSf));
    float a1 = sqrtf(fmaxf(pd1, EPSf) * fmaxf(ps1, EPSf));
    ((float2*)g_asort)[g_posof[e]] = make_float2(a0, a1);
}

// ---------------- h0 feat_trans + hop-attn left term --------------------------
__global__ void k_h0al(const float* __restrict__ scale, const float* __restrict__ offset,
                       const float* __restrict__ pemb,  const float* __restrict__ hal) {
    int w = blockIdx.x * (blockDim.x >> 5) + (threadIdx.x >> 5);
    if (w >= Nn * Hh) return;
    int n = w >> 1, head = w & 1;
    int lane = threadIdx.x & 31;
    float2 x = *(const float2*)(g_hsrc + (size_t)n * HD + head * Dd + lane * 2);
    float s = x.x + x.y, q = x.x * x.x + x.y * x.y;
#pragma unroll
    for (int o = 16; o; o >>= 1) {
        s += __shfl_xor_sync(0xffffffffu, s, o);
        q += __shfl_xor_sync(0xffffffffu, q, o);
    }
    float mean = s * (1.f / 64.f);
    float var  = q * (1.f / 64.f) - mean * mean + EPSf;
    float rs = rsqrtf(var);
    int bi = head * Dd + lane * 2;
    float2 sc = *(const float2*)(scale + bi);
    float2 of = *(const float2*)(offset + bi);
    float2 pe = *(const float2*)(pemb + bi);
    float2 hl = *(const float2*)(hal + bi);
    float n0 = (x.x - mean) * sc.x * rs + of.x + pe.x;
    float n1 = (x.y - mean) * sc.y * rs + of.y + pe.y;
    float p = n0 * hl.x + n1 * hl.y;
#pragma unroll
    for (int o = 16; o; o >>= 1) p += __shfl_xor_sync(0xffffffffu, p, o);
    if (lane == 0) g_al[w] = p;
}

// ---------------- diffusion hop: pull-gather + fused feat_trans ----------------
__global__ void k_hop(int hop, const float* __restrict__ scale,
                      const float* __restrict__ offset, const float* __restrict__ pemb) {
    int n = blockIdx.x * (blockDim.x >> 5) + (threadIdx.x >> 5);
    if (n >= Nn) return;
    int lane = threadIdx.x & 31;
    int head = lane >> 4;
    const float* __restrict__ hin = (hop == 0) ? g_hsrc : (hop == 1 ? g_h0buf : g_h1buf);
    float* hout = (hop & 1) ? g_h1buf : g_h0buf;

    int start = g_rowptr[n], end = g_rowptr[n + 1];
    int srcl = head << 4;
    float4 acc = make_float4(0.f, 0.f, 0.f, 0.f);
    for (int base = start; base < end; base += 16) {
        int cnt = end - base; if (cnt > 16) cnt = 16;
        int el = lane & 15;
        int s = 0; float coef = 0.f;
        if (el < cnt) {
            int e = base + el;
            s    = g_colsrc[e];
            coef = g_asort[2 * e + head];
        }
        int j = 0;
        for (; j + 4 <= cnt; j += 4) {
            int   s0 = __shfl_sync(0xffffffffu, s, j);
            int   s1 = __shfl_sync(0xffffffffu, s, j + 1);
            int   s2 = __shfl_sync(0xffffffffu, s, j + 2);
            int   s3 = __shfl_sync(0xffffffffu, s, j + 3);
            float a0 = __shfl_sync(0xffffffffu, coef, srcl + j);
            float a1 = __shfl_sync(0xffffffffu, coef, srcl + j + 1);
            float a2 = __shfl_sync(0xffffffffu, coef, srcl + j + 2);
            float a3 = __shfl_sync(0xffffffffu, coef, srcl + j + 3);
            float4 v0 = *(const float4*)(hin + (size_t)s0 * HD + lane * 4);
            float4 v1 = *(const float4*)(hin + (size_t)s1 * HD + lane * 4);
            float4 v2 = *(const float4*)(hin + (size_t)s2 * HD + lane * 4);
            float4 v3 = *(const float4*)(hin + (size_t)s3 * HD + lane * 4);
            acc.x += a0 * v0.x + a1 * v1.x + a2 * v2.x + a3 * v3.x;
            acc.y += a0 * v0.y + a1 * v1.y + a2 * v2.y + a3 * v3.y;
            acc.z += a0 * v0.z + a1 * v1.z + a2 * v2.z + a3 * v3.z;
            acc.w += a0 * v0.w + a1 * v1.w + a2 * v2.w + a3 * v3.w;
        }
        for (; j < cnt; j++) {
            int   ss = __shfl_sync(0xffffffffu, s, j);
            float aa = __shfl_sync(0xffffffffu, coef, srcl + j);
            float4 v = *(const float4*)(hin + (size_t)ss * HD + lane * 4);
            acc.x += aa * v.x; acc.y += aa * v.y; acc.z += aa * v.z; acc.w += aa * v.w;
        }
    }
    *(float4*)(hout + (size_t)n * HD + lane * 4) = acc;

    float s1 = acc.x + acc.y + acc.z + acc.w;
    float q1 = acc.x * acc.x + acc.y * acc.y + acc.z * acc.z + acc.w * acc.w;
#pragma unroll
    for (int o = 1; o < 16; o <<= 1) {
        s1 += __shfl_xor_sync(0xffffffffu, s1, o);
        q1 += __shfl_xor_sync(0xffffffffu, q1, o);
    }
    float mean = s1 * (1.f / 64.f);
    float var  = q1 * (1.f / 64.f) - mean * mean + EPSf;
    float rs = rsqrtf(var);
    int k = hop + 1;
    int d0 = (lane & 15) * 4;
    int pi = (k * Hh + head) * Dd + d0;
    float4 sc = *(const float4*)(scale + pi);
    float4 of = *(const float4*)(offset + pi);
    float4 pe = *(const float4*)(pemb + pi);
    float4 ov;
    ov.x = (acc.x - mean) * sc.x * rs + of.x + pe.x;
    ov.y = (acc.y - mean) * sc.y * rs + of.y + pe.y;
    ov.z = (acc.z - mean) * sc.z * rs + of.z + pe.z;
    ov.w = (acc.w - mean) * sc.w * rs + of.w + pe.w;
    *(float4*)(g_hstack + ((((size_t)n * Hh + head) * Kk) + hop) * Dd + d0) = ov;
}

// ---------------- hop attention + residual ------------------------------------
__global__ void k_final(const float* __restrict__ war, float* __restrict__ out) {
    int n = blockIdx.x * (blockDim.x >> 5) + (threadIdx.x >> 5);
    if (n >= Nn) return;
    int lane = threadIdx.x & 31;
    int head = lane >> 4, d0 = (lane & 15) * 4;
    float4 wr = *(const float4*)(war + head * Dd + d0);
    float al = g_al[n * 2 + head];
    float4 v[3]; float ha[3];
#pragma unroll
    for (int k = 0; k < 3; k++) {
        v[k] = *(const float4*)(g_hstack + ((((size_t)n * Hh + head) * Kk) + k) * Dd + d0);
        float p = v[k].x * wr.x + v[k].y * wr.y + v[k].z * wr.z + v[k].w * wr.w;
#pragma unroll
        for (int o = 1; o < 16; o <<= 1) p += __shfl_xor_sync(0xffffffffu, p, o);
        ha[k] = lrelu(p + al);
    }
    float m = fmaxf(ha[0], fmaxf(ha[1], ha[2]));
    float e0 = __expf(ha[0] - m), e1 = __expf(ha[1] - m), e2 = __expf(ha[2] - m);
    float inv = 1.f / (e0 + e1 + e2);
    float s0 = e0 * inv, s1 = e1 * inv, s2 = e2 * inv;
    float4 hd = *(const float4*)(g_hdst + (size_t)n * HD + lane * 4);
    float4 o4;
    o4.x = hd.x + s0 * v[0].x + s1 * v[1].x + s2 * v[2].x;
    o4.y = hd.y + s0 * v[0].y + s1 * v[1].y + s2 * v[2].y;
    o4.z = hd.z + s0 * v[0].z + s1 * v[1].z + s2 * v[2].z;
    o4.w = hd.w + s0 * v[0].w + s1 * v[1].w + s2 * v[2].w;
    *(float4*)(out + (size_t)n * HD + lane * 4) = o4;
}

// ---------------- launch -------------------------------------------------------
extern "C" void kernel_launch(void* const* d_in, const int* in_sizes, int n_in,
                              void* d_out, int out_size) {
    const float* feat  = (const float*)d_in[0];
    const int*   src   = (const int*)d_in[1];
    const int*   dst   = (const int*)d_in[2];
    const float* Wsrc  = (const float*)d_in[3];
    const float* Wdst  = (const float*)d_in[4];
    const float* bdst  = (const float*)d_in[5];
    const float* Was   = (const float*)d_in[6];
    const float* Wad   = (const float*)d_in[7];
    const float* scale = (const float*)d_in[8];
    const float* offs  = (const float*)d_in[9];
    const float* pemb  = (const float*)d_in[10];
    const float* hal   = (const float*)d_in[11];
    const float* war   = (const float*)d_in[12];
    float* out = (float*)d_out;
    (void)in_sizes; (void)n_in; (void)out_size;

    k_init<<<(Nn * Hh + 255) / 256, 256>>>();

    dim3 gg(1, (Nn + 127) / 128, 2);
    k_gemm<<<gg, 256>>>(feat, Wsrc, Wdst, bdst);
    k_attnproj<<<(Nn + 7) / 8, 256>>>(feat, Was, Wad);

    int eb = (Ee + 255) / 256;
    k_hist<<<eb, 256>>>(dst);
    k_scan<<<1, 1024>>>();
    k_scatter_sum<<<eb, 256>>>(src, dst);
    k_edge_coef<<<eb, 256>>>(src, dst);

    k_h0al<<<(Nn * Hh + 7) / 8, 256>>>(scale, offs, pemb, hal);

    for (int hop = 0; hop < Kk; hop++)
        k_hop<<<(Nn + 7) / 8, 256>>>(hop, scale, offs, pemb);

    k_final<<<(Nn + 7) / 8, 256>>>(war, out);
}